// round 3
// baseline (speedup 1.0000x reference)
#include <cuda_runtime.h>
#include <math.h>

// ---------------- problem constants (from setup_inputs) ----------------
#define DD     128
#define HHEADS 16
#define MAXN   50000
#define MAXE   500000

// ---------------- scratch (__device__ globals; no allocs allowed) ------
__device__ float g_xl [MAXN * DD];              // xl for current conv
__device__ float g_xr [MAXN * DD];              // xr for current conv
__device__ float g_me1[MAXE * DD];              // dual_attr @ We1
__device__ float g_elog[MAXE * HHEADS];         // logits -> exp values
__device__ float g_smax[MAXN * HHEADS];
__device__ float g_ssum[MAXN * HHEADS];
__device__ float g_cat [MAXN * 4 * DD];         // concat(x1..x4) (bias pre-filled)

// ---------------- helpers ----------------
__device__ __forceinline__ void atomicMaxF(float* addr, float v) {
    if (v >= 0.f) atomicMax((int*)addr, __float_as_int(v));
    else          atomicMin((unsigned int*)addr, __float_as_uint(v));
}

__global__ void fill_kernel(float* __restrict__ p, float v, int n) {
    int i = blockIdx.x * 256 + threadIdx.x;
    if (i < n) p[i] = v;
}

// init cat[:, c*128:(c+1)*128] = bias (row stride 512)
__global__ void fill_bias_kernel(float* __restrict__ cat, const float* __restrict__ bias, int N) {
    int i = blockIdx.x * 256 + threadIdx.x;
    if (i >= N * DD) return;
    int n = i >> 7, cc = i & 127;
    cat[(size_t)n * 512 + cc] = bias[cc];
}

// ---------------- generic tiled SGEMM: C[M,N] = A[M,K] @ B[K,N] (+bias) -
// BM=BN=64, BK=16, 256 threads, 4x4 per thread. K % 16 == 0, N % 64 == 0.
__global__ void sgemm_kernel(const float* __restrict__ A, const float* __restrict__ B,
                             float* __restrict__ C, int M, int N, int K,
                             const float* __restrict__ bias) {
    __shared__ float As[64][16];
    __shared__ float Bs[16][64];
    int tid = threadIdx.x;
    int tx = tid & 15, ty = tid >> 4;
    int row0 = blockIdx.y * 64, col0 = blockIdx.x * 64;
    float acc[4][4] = {};
    for (int k0 = 0; k0 < K; k0 += 16) {
        for (int i = tid; i < 64 * 16; i += 256) {
            int r = i >> 4, c = i & 15;
            int gr = row0 + r;
            As[r][c] = (gr < M) ? A[(size_t)gr * K + k0 + c] : 0.f;
        }
        for (int i = tid; i < 16 * 64; i += 256) {
            int r = i >> 6, c = i & 63;
            Bs[r][c] = B[(size_t)(k0 + r) * N + col0 + c];
        }
        __syncthreads();
#pragma unroll
        for (int kk = 0; kk < 16; kk++) {
            float a0 = As[ty * 4 + 0][kk];
            float a1 = As[ty * 4 + 1][kk];
            float a2 = As[ty * 4 + 2][kk];
            float a3 = As[ty * 4 + 3][kk];
            float4 bv = *(const float4*)&Bs[kk][tx * 4];
            acc[0][0] += a0 * bv.x; acc[0][1] += a0 * bv.y; acc[0][2] += a0 * bv.z; acc[0][3] += a0 * bv.w;
            acc[1][0] += a1 * bv.x; acc[1][1] += a1 * bv.y; acc[1][2] += a1 * bv.z; acc[1][3] += a1 * bv.w;
            acc[2][0] += a2 * bv.x; acc[2][1] += a2 * bv.y; acc[2][2] += a2 * bv.z; acc[2][3] += a2 * bv.w;
            acc[3][0] += a3 * bv.x; acc[3][1] += a3 * bv.y; acc[3][2] += a3 * bv.z; acc[3][3] += a3 * bv.w;
        }
        __syncthreads();
    }
#pragma unroll
    for (int i = 0; i < 4; i++) {
        int gr = row0 + ty * 4 + i;
        if (gr < M) {
#pragma unroll
            for (int j = 0; j < 4; j++) {
                int gc = col0 + tx * 4 + j;
                float bv = bias ? bias[gc] : 0.f;
                C[(size_t)gr * N + gc] = acc[i][j] + bv;
            }
        }
    }
}

// ---------------- edge logits: warp per edge ----------------
__global__ void edge_logits_kernel(const int* __restrict__ src, const int* __restrict__ dst, int E,
                                   const float* __restrict__ xl, const float* __restrict__ xr,
                                   const float* __restrict__ me, const float* __restrict__ att,
                                   float* __restrict__ elog, float* __restrict__ smax) {
    int e = blockIdx.x * 8 + (threadIdx.x >> 5);
    int lane = threadIdx.x & 31;
    if (e >= E) return;
    int s = src[e], d = dst[e];
    float4 a = *(const float4*)(xl + (size_t)s * DD + lane * 4);
    float4 b = *(const float4*)(xr + (size_t)d * DD + lane * 4);
    float4 mv = make_float4(a.x + b.x, a.y + b.y, a.z + b.z, a.w + b.w);
    if (me) {
        float4 c = *(const float4*)(me + (size_t)e * DD + lane * 4);
        mv.x += c.x; mv.y += c.y; mv.z += c.z; mv.w += c.w;
    }
    float4 at = *(const float4*)(att + lane * 4);
    float p = 0.f, m;
    m = mv.x; m = m > 0.f ? m : 0.2f * m; p += m * at.x;
    m = mv.y; m = m > 0.f ? m : 0.2f * m; p += m * at.y;
    m = mv.z; m = m > 0.f ? m : 0.2f * m; p += m * at.z;
    m = mv.w; m = m > 0.f ? m : 0.2f * m; p += m * at.w;
    p += __shfl_xor_sync(0xffffffffu, p, 1);
    if ((lane & 1) == 0) {
        int h = lane >> 1;
        elog[(size_t)e * HHEADS + h] = p;
        atomicMaxF(&smax[d * HHEADS + h], p);
    }
}

// ---------------- exp + segment-sum ----------------
__global__ void edge_exp_kernel(const int* __restrict__ dst, int E,
                                float* __restrict__ elog, const float* __restrict__ smax,
                                float* __restrict__ ssum) {
    int t = blockIdx.x * 256 + threadIdx.x;
    if (t >= E * HHEADS) return;
    int e = t >> 4, h = t & 15;
    int d = dst[e];
    float v = __expf(elog[t] - smax[d * HHEADS + h]);
    elog[t] = v;
    atomicAdd(&ssum[d * HHEADS + h], v);
}

// ---------------- weighted scatter-aggregate (into strided cat buffer) --
__global__ void edge_agg_kernel(const int* __restrict__ src, const int* __restrict__ dst, int E,
                                const float* __restrict__ elog, const float* __restrict__ ssum,
                                const float* __restrict__ xl, float* __restrict__ agg /*stride 512*/) {
    int e = blockIdx.x * 8 + (threadIdx.x >> 5);
    int lane = threadIdx.x & 31;
    if (e >= E) return;
    int s = src[e], d = dst[e];
    int h = lane >> 1;
    float al = elog[(size_t)e * HHEADS + h] / (ssum[d * HHEADS + h] + 1e-16f);
    float4 xs = *(const float4*)(xl + (size_t)s * DD + lane * 4);
    float* base = agg + (size_t)d * 512 + lane * 4;
    atomicAdd(base + 0, al * xs.x);
    atomicAdd(base + 1, al * xs.y);
    atomicAdd(base + 2, al * xs.z);
    atomicAdd(base + 3, al * xs.w);
}

// ---------------- fused edge MLP: gather pair -> LN -> ReLU -> GEMM -> +attr
// block: 256 threads, 32 edges. smem: P 32KB + Wt 16KB = 48KB.
__global__ void edge_mlp_kernel(const float* __restrict__ xf,
                                const int* __restrict__ src, const int* __restrict__ dst,
                                const float* __restrict__ ln_g, const float* __restrict__ ln_b,
                                const float* __restrict__ mlp_W, const float* __restrict__ mlp_b,
                                const float* __restrict__ eattr, float* __restrict__ out, int E) {
    __shared__ float P[32][256];
    __shared__ float Wt[32][128];
    int tid = threadIdx.x;
    int e0 = blockIdx.x * 32;
    for (int i = tid; i < 32 * 256; i += 256) {
        int el = i >> 8, col = i & 255;
        int e = e0 + el;
        float v = 0.f;
        if (e < E) {
            int n = (col < 128) ? src[e] : dst[e];
            v = xf[(size_t)n * DD + (col & 127)];
        }
        P[el][col] = v;
    }
    __syncthreads();
    int wid = tid >> 5, lane = tid & 31;
    for (int r = wid * 4; r < wid * 4 + 4; r++) {
        float s = 0.f, s2 = 0.f;
        for (int c = lane; c < 256; c += 32) { float v = P[r][c]; s += v; s2 += v * v; }
#pragma unroll
        for (int o = 16; o; o >>= 1) {
            s  += __shfl_xor_sync(0xffffffffu, s,  o);
            s2 += __shfl_xor_sync(0xffffffffu, s2, o);
        }
        float mu = s * (1.f / 256.f);
        float var = s2 * (1.f / 256.f) - mu * mu;
        float rstd = rsqrtf(var + 1e-5f);
        for (int c = lane; c < 256; c += 32) {
            float v = (P[r][c] - mu) * rstd * ln_g[c] + ln_b[c];
            P[r][c] = v > 0.f ? v : 0.f;
        }
    }
    __syncthreads();
    int tx = tid & 31, ty = tid >> 5;
    float acc[4][4] = {};
    for (int k0 = 0; k0 < 256; k0 += 32) {
        for (int i = tid; i < 32 * 128; i += 256) {
            int r = i >> 7, c = i & 127;
            Wt[r][c] = mlp_W[(size_t)(k0 + r) * 128 + c];
        }
        __syncthreads();
#pragma unroll
        for (int kk = 0; kk < 32; kk++) {
            float4 bv = *(const float4*)&Wt[kk][tx * 4];
#pragma unroll
            for (int i = 0; i < 4; i++) {
                float a = P[ty * 4 + i][k0 + kk];
                acc[i][0] += a * bv.x; acc[i][1] += a * bv.y;
                acc[i][2] += a * bv.z; acc[i][3] += a * bv.w;
            }
        }
        __syncthreads();
    }
#pragma unroll
    for (int i = 0; i < 4; i++) {
        int e = e0 + ty * 4 + i;
        if (e < E) {
#pragma unroll
            for (int j = 0; j < 4; j++) {
                int c = tx * 4 + j;
                out[(size_t)e * DD + c] = acc[i][j] + mlp_b[c] + eattr[(size_t)e * DD + c];
            }
        }
    }
}

// ---------------- dual gather ----------------
__global__ void dual_gather_kernel(const float* __restrict__ e_new, const int* __restrict__ idx,
                                   float* __restrict__ out, int E) {
    int row = blockIdx.x;
    int id = idx[row];
    float v = (id < E) ? e_new[(size_t)id * DD + threadIdx.x] : 1.0f;
    out[(size_t)row * DD + threadIdx.x] = v;
}

// ======================= launch =======================
extern "C" void kernel_launch(void* const* d_in, const int* in_sizes, int n_in,
                              void* d_out, int out_size) {
    const float* x         = (const float*)d_in[0];
    const int*   ei1       = (const int*)d_in[1];
    const int*   ei2       = (const int*)d_in[2];
    const int*   ei4       = (const int*)d_in[3];
    const int*   ei8       = (const int*)d_in[4];
    const float* dual_attr = (const float*)d_in[5];
    const float* edge_attr = (const float*)d_in[6];
    const int*   oemap     = (const int*)d_in[7];
    const float* Wl[4]  = {(const float*)d_in[8],  (const float*)d_in[12], (const float*)d_in[16], (const float*)d_in[20]};
    const float* Wr[4]  = {(const float*)d_in[9],  (const float*)d_in[13], (const float*)d_in[17], (const float*)d_in[21]};
    const float* att[4] = {(const float*)d_in[10], (const float*)d_in[14], (const float*)d_in[18], (const float*)d_in[22]};
    const float* bb[4]  = {(const float*)d_in[11], (const float*)d_in[15], (const float*)d_in[19], (const float*)d_in[23]};
    const float* We1    = (const float*)d_in[24];
    const float* fuse_W = (const float*)d_in[25];
    const float* fuse_b = (const float*)d_in[26];
    const float* ln_g   = (const float*)d_in[27];
    const float* ln_b   = (const float*)d_in[28];
    const float* mlp_W  = (const float*)d_in[29];
    const float* mlp_b  = (const float*)d_in[30];

    int N  = in_sizes[0] / DD;
    int Ec[4] = { in_sizes[1] / 2, in_sizes[2] / 2, in_sizes[3] / 2, in_sizes[4] / 2 };
    const int* eis[4] = { ei1, ei2, ei4, ei8 };
    int E   = Ec[0];
    int Moe = in_sizes[7];

    float* xf_out   = (float*)d_out;
    float* enew_out = xf_out + (size_t)N * DD;
    float* dual_out = enew_out + (size_t)E * DD;

    float *p_xl, *p_xr, *p_me1, *p_elog, *p_smax, *p_ssum, *p_cat;
    cudaGetSymbolAddress((void**)&p_xl,   g_xl);
    cudaGetSymbolAddress((void**)&p_xr,   g_xr);
    cudaGetSymbolAddress((void**)&p_me1,  g_me1);
    cudaGetSymbolAddress((void**)&p_elog, g_elog);
    cudaGetSymbolAddress((void**)&p_smax, g_smax);
    cudaGetSymbolAddress((void**)&p_ssum, g_ssum);
    cudaGetSymbolAddress((void**)&p_cat,  g_cat);

    // me1 = dual_attr @ We1 : [E,128]
    {
        dim3 grid(2, (E + 63) / 64);
        sgemm_kernel<<<grid, 256>>>(dual_attr, We1, p_me1, E, 128, 128, nullptr);
    }

    // 4 GAT convs, sequential, aggregating into g_cat[:, c*128:(c+1)*128]
    dim3 ggrid(2, (N + 63) / 64);
    for (int c = 0; c < 4; c++) {
        int Ecc = Ec[c];
        const int* src = eis[c];
        const int* dst = eis[c] + Ecc;

        sgemm_kernel<<<ggrid, 256>>>(x, Wl[c], p_xl, N, 128, 128, nullptr);
        sgemm_kernel<<<ggrid, 256>>>(x, Wr[c], p_xr, N, 128, 128, nullptr);

        fill_bias_kernel<<<(N * DD + 255) / 256, 256>>>(p_cat + (size_t)c * DD, bb[c], N);
        fill_kernel<<<(N * HHEADS + 255) / 256, 256>>>(p_smax, -INFINITY, N * HHEADS);
        fill_kernel<<<(N * HHEADS + 255) / 256, 256>>>(p_ssum, 0.f, N * HHEADS);

        edge_logits_kernel<<<(Ecc + 7) / 8, 256>>>(src, dst, Ecc, p_xl, p_xr,
                                                   (c == 0) ? p_me1 : nullptr,
                                                   att[c], p_elog, p_smax);
        edge_exp_kernel<<<(Ecc * HHEADS + 255) / 256, 256>>>(dst, Ecc, p_elog, p_smax, p_ssum);
        edge_agg_kernel<<<(Ecc + 7) / 8, 256>>>(src, dst, Ecc, p_elog, p_ssum, p_xl,
                                                p_cat + (size_t)c * DD);
    }

    // fuse GEMM: xf = cat @ fuse_W + fuse_b
    sgemm_kernel<<<ggrid, 256>>>(p_cat, fuse_W, xf_out, N, 128, 512, fuse_b);

    // edge MLP (+residual) -> enew_out
    edge_mlp_kernel<<<(E + 31) / 32, 256>>>(xf_out, ei1, ei1 + E, ln_g, ln_b,
                                            mlp_W, mlp_b, edge_attr, enew_out, E);

    // dual gather
    dual_gather_kernel<<<Moe, DD>>>(enew_out, oemap, dual_out, E);
}

// round 5
// speedup vs baseline: 1.5855x; 1.5855x over previous
#include <cuda_runtime.h>
#include <cuda_bf16.h>
#include <math.h>
#include <stdint.h>

// ---------------- problem constants ----------------
#define DD     128
#define HHEADS 16
#define MAXN   50000
#define MAXE   500000

// ---------------- scratch (__device__ globals; no allocs allowed) ------
__device__ float g_me1 [MAXE * DD];                  // dual_attr @ We1 (fp32)
__device__ float g_xl  [MAXN * DD];
__device__ float g_xr  [MAXN * DD];
__device__ float g_elog[MAXE * HHEADS];
__device__ float g_smax[MAXN * HHEADS];
__device__ float g_ssum[MAXN * HHEADS];
__device__ float g_cat [MAXN * 4 * DD];
// big bf16 hi/lo activation buffers: dual_attr split (E*128) early, pair (E*256) late
__device__ __nv_bfloat16 g_bh[MAXE * 256];
__device__ __nv_bfloat16 g_bl[MAXE * 256];
// node-side splits: x (N*128) then cat (N*512)
__device__ __nv_bfloat16 g_nh[MAXN * 512];
__device__ __nv_bfloat16 g_nl[MAXN * 512];
// weights, bf16 hi/lo, transposed to [N=128, K] K-major
#define WB_TOTAL 245760
__device__ __nv_bfloat16 g_Whi[WB_TOTAL];
__device__ __nv_bfloat16 g_Wlo[WB_TOTAL];

// ---------------- small helpers ----------------
__device__ __forceinline__ uint32_t smem_to_u32(const void* p) {
    uint32_t a;
    asm("{ .reg .u64 t; cvta.to.shared.u64 t, %1; cvt.u32.u64 %0, t; }" : "=r"(a) : "l"(p));
    return a;
}
__device__ __forceinline__ void atomicMaxF(float* addr, float v) {
    if (v >= 0.f) atomicMax((int*)addr, __float_as_int(v));
    else          atomicMin((unsigned int*)addr, __float_as_uint(v));
}

__device__ __forceinline__ void ldsm_x4(uint32_t addr, uint32_t* r) {
    asm volatile("ldmatrix.sync.aligned.m8n8.x4.shared.b16 {%0,%1,%2,%3}, [%4];"
                 : "=r"(r[0]), "=r"(r[1]), "=r"(r[2]), "=r"(r[3]) : "r"(addr));
}
__device__ __forceinline__ void mma_bf16(float* c, const uint32_t* a, const uint32_t* b) {
    asm volatile("mma.sync.aligned.m16n8k16.row.col.f32.bf16.bf16.f32 "
                 "{%0,%1,%2,%3}, {%4,%5,%6,%7}, {%8,%9}, {%0,%1,%2,%3};"
                 : "+f"(c[0]), "+f"(c[1]), "+f"(c[2]), "+f"(c[3])
                 : "r"(a[0]), "r"(a[1]), "r"(a[2]), "r"(a[3]), "r"(b[0]), "r"(b[1]));
}

// ============ bf16x3 HMMA GEMM ============
// C[M,128] = A[M,K] @ W[K,128]; A given split hi/lo bf16 row-major [M,K];
// W given split hi/lo bf16 as [128,K] K-major. fp32 accumulate.
// BM=BN=128, BK=64, 256 threads (8 warps of 32x64 tiles). smem 64KB swizzled.
#define SMA_HI 0
#define SMA_LO 16384
#define SMB_HI 32768
#define SMB_LO 49152
#define GEMM_SMEM 65536

__global__ void __launch_bounds__(256, 1) mma_gemm_kernel(
    const __nv_bfloat16* __restrict__ Ahi, const __nv_bfloat16* __restrict__ Alo,
    int M, int Ktot,
    const __nv_bfloat16* __restrict__ Bhi, const __nv_bfloat16* __restrict__ Blo,
    const float* __restrict__ bias, const float* __restrict__ res,
    float* __restrict__ C)
{
    extern __shared__ char smem[];
    uint32_t sb = smem_to_u32(smem);
    int tid = threadIdx.x, warp = tid >> 5, lane = tid & 31;
    int m0 = blockIdx.x * 128;
    int wm = (warp & 3) << 5, wn = (warp >> 2) << 6;
    int kt8 = Ktot >> 3;

    float acc[2][8][4];
#pragma unroll
    for (int i = 0; i < 2; i++)
#pragma unroll
        for (int j = 0; j < 8; j++)
#pragma unroll
            for (int q = 0; q < 4; q++) acc[i][j][q] = 0.f;

    const uint4 zero4 = make_uint4(0, 0, 0, 0);
    int nchunk = Ktot >> 6;
    for (int ch = 0; ch < nchunk; ch++) {
        if (ch) __syncthreads();
        int k8 = ch << 3;   // chunk start in uint4 units (8 bf16)
        // ---- load chunk into swizzled smem ----
        for (int t = tid; t < 1024; t += 256) {
            int row = t >> 3, seg = t & 7;
            uint32_t soff = (uint32_t)(row * 128 + ((seg ^ (row & 7)) << 4));
            int gr = m0 + row;
            uint4 vh = zero4, vl = zero4;
            if (gr < M) {
                size_t gi = (size_t)gr * kt8 + k8 + seg;
                vh = ((const uint4*)Ahi)[gi];
                vl = ((const uint4*)Alo)[gi];
            }
            *(uint4*)(smem + SMA_HI + soff) = vh;
            *(uint4*)(smem + SMA_LO + soff) = vl;
            size_t bi = (size_t)row * kt8 + k8 + seg;
            *(uint4*)(smem + SMB_HI + soff) = ((const uint4*)Bhi)[bi];
            *(uint4*)(smem + SMB_LO + soff) = ((const uint4*)Blo)[bi];
        }
        __syncthreads();

        // ---- compute: 4 k16 steps ----
#pragma unroll
        for (int ks = 0; ks < 4; ks++) {
            uint32_t ah[2][4], al[2][4];
#pragma unroll
            for (int mi = 0; mi < 2; mi++) {
                int row = wm + mi * 16 + (lane & 15);
                int seg = ks * 2 + (lane >> 4);
                uint32_t ao = sb + (uint32_t)(row * 128 + ((seg ^ (row & 7)) << 4));
                ldsm_x4(ao + SMA_HI, ah[mi]);
                ldsm_x4(ao + SMA_LO, al[mi]);
            }
            uint32_t bh[8][2], bl[8][2];
#pragma unroll
            for (int nj = 0; nj < 8; nj += 2) {
                int n = wn + nj * 8 + ((lane >> 3) & 1) * 8 + (lane & 7);
                int seg = ks * 2 + (lane >> 4);
                uint32_t bo = sb + (uint32_t)(n * 128 + ((seg ^ (n & 7)) << 4));
                uint32_t th[4], tl[4];
                ldsm_x4(bo + SMB_HI, th);
                ldsm_x4(bo + SMB_LO, tl);
                bh[nj][0] = th[0]; bh[nj + 1][0] = th[1]; bh[nj][1] = th[2]; bh[nj + 1][1] = th[3];
                bl[nj][0] = tl[0]; bl[nj + 1][0] = tl[1]; bl[nj][1] = tl[2]; bl[nj + 1][1] = tl[3];
            }
#pragma unroll
            for (int mi = 0; mi < 2; mi++)
#pragma unroll
                for (int ni = 0; ni < 8; ni++) {
                    mma_bf16(acc[mi][ni], ah[mi], bh[ni]);
                    mma_bf16(acc[mi][ni], al[mi], bh[ni]);
                    mma_bf16(acc[mi][ni], ah[mi], bl[ni]);
                }
        }
    }

    // ---- epilogue ----
    int r0 = (lane >> 2), c0 = (lane & 3) * 2;
#pragma unroll
    for (int mi = 0; mi < 2; mi++) {
#pragma unroll
        for (int ni = 0; ni < 8; ni++) {
            int col = wn + ni * 8 + c0;
            float bx = 0.f, by = 0.f;
            if (bias) { bx = bias[col]; by = bias[col + 1]; }
#pragma unroll
            for (int h = 0; h < 2; h++) {
                int row = m0 + wm + mi * 16 + r0 + h * 8;
                if (row < M) {
                    float vx = acc[mi][ni][h * 2 + 0] + bx;
                    float vy = acc[mi][ni][h * 2 + 1] + by;
                    size_t oi = (size_t)row * 128 + col;
                    if (res) { vx += res[oi]; vy += res[oi + 1]; }
                    *(float2*)(C + oi) = make_float2(vx, vy);
                }
            }
        }
    }
}

// ============ weight prep: W[K,128] fp32 -> hi/lo bf16 [128,K] ============
__global__ void wprep_kernel(const float* __restrict__ W, __nv_bfloat16* __restrict__ hi,
                             __nv_bfloat16* __restrict__ lo, int K) {
    int i = blockIdx.x * 256 + threadIdx.x;
    if (i >= K * 128) return;
    int n = i / K, k = i - n * K;
    float v = W[(size_t)k * 128 + n];
    __nv_bfloat16 h = __float2bfloat16(v);
    hi[i] = h;
    lo[i] = __float2bfloat16(v - __bfloat162float(h));
}

// ============ activation split: fp32 -> hi/lo bf16 (same layout) ============
__global__ void asplit_kernel(const float* __restrict__ A, __nv_bfloat16* __restrict__ hi,
                              __nv_bfloat16* __restrict__ lo, int n4) {
    int i = blockIdx.x * 256 + threadIdx.x;
    if (i >= n4) return;
    float4 v = ((const float4*)A)[i];
    union { __nv_bfloat16 b[4]; uint2 u; } hu, lu;
    float f[4] = { v.x, v.y, v.z, v.w };
#pragma unroll
    for (int j = 0; j < 4; j++) {
        __nv_bfloat16 h = __float2bfloat16(f[j]);
        hu.b[j] = h;
        lu.b[j] = __float2bfloat16(f[j] - __bfloat162float(h));
    }
    ((uint2*)hi)[i] = hu.u;
    ((uint2*)lo)[i] = lu.u;
}

// ---------------- misc fills ----------------
__global__ void fill_kernel(float* __restrict__ p, float v, int n) {
    int i = blockIdx.x * 256 + threadIdx.x;
    if (i < n) p[i] = v;
}
__global__ void fill_bias_kernel(float* __restrict__ cat, const float* __restrict__ bias, int N) {
    int i = blockIdx.x * 256 + threadIdx.x;
    if (i >= N * DD) return;
    int n = i >> 7, cc = i & 127;
    cat[(size_t)n * 512 + cc] = bias[cc];
}

// ---------------- edge logits ----------------
__global__ void edge_logits_kernel(const int* __restrict__ src, const int* __restrict__ dst, int E,
                                   const float* __restrict__ xl, const float* __restrict__ xr,
                                   const float* __restrict__ me, const float* __restrict__ att,
                                   float* __restrict__ elog, float* __restrict__ smax) {
    int e = blockIdx.x * 8 + (threadIdx.x >> 5);
    int lane = threadIdx.x & 31;
    if (e >= E) return;
    int s = src[e], d = dst[e];
    float4 a = *(const float4*)(xl + (size_t)s * DD + lane * 4);
    float4 b = *(const float4*)(xr + (size_t)d * DD + lane * 4);
    float4 mv = make_float4(a.x + b.x, a.y + b.y, a.z + b.z, a.w + b.w);
    if (me) {
        float4 c = *(const float4*)(me + (size_t)e * DD + lane * 4);
        mv.x += c.x; mv.y += c.y; mv.z += c.z; mv.w += c.w;
    }
    float4 at = *(const float4*)(att + lane * 4);
    float p = 0.f, m;
    m = mv.x; m = m > 0.f ? m : 0.2f * m; p += m * at.x;
    m = mv.y; m = m > 0.f ? m : 0.2f * m; p += m * at.y;
    m = mv.z; m = m > 0.f ? m : 0.2f * m; p += m * at.z;
    m = mv.w; m = m > 0.f ? m : 0.2f * m; p += m * at.w;
    p += __shfl_xor_sync(0xffffffffu, p, 1);
    if ((lane & 1) == 0) {
        int h = lane >> 1;
        elog[(size_t)e * HHEADS + h] = p;
        atomicMaxF(&smax[d * HHEADS + h], p);
    }
}

__global__ void edge_exp_kernel(const int* __restrict__ dst, int E,
                                float* __restrict__ elog, const float* __restrict__ smax,
                                float* __restrict__ ssum) {
    int t = blockIdx.x * 256 + threadIdx.x;
    if (t >= E * HHEADS) return;
    int e = t >> 4, h = t & 15;
    int d = dst[e];
    float v = __expf(elog[t] - smax[d * HHEADS + h]);
    elog[t] = v;
    atomicAdd(&ssum[d * HHEADS + h], v);
}

__global__ void edge_agg_kernel(const int* __restrict__ src, const int* __restrict__ dst, int E,
                                const float* __restrict__ elog, const float* __restrict__ ssum,
                                const float* __restrict__ xl, float* __restrict__ agg /*stride 512*/) {
    int e = blockIdx.x * 8 + (threadIdx.x >> 5);
    int lane = threadIdx.x & 31;
    if (e >= E) return;
    int s = src[e], d = dst[e];
    int h = lane >> 1;
    float al = elog[(size_t)e * HHEADS + h] / (ssum[d * HHEADS + h] + 1e-16f);
    float4 xs = *(const float4*)(xl + (size_t)s * DD + lane * 4);
    float* base = agg + (size_t)d * 512 + lane * 4;
    atomicAdd(base + 0, al * xs.x);
    atomicAdd(base + 1, al * xs.y);
    atomicAdd(base + 2, al * xs.z);
    atomicAdd(base + 3, al * xs.w);
}

// ---------------- LN over gathered pairs -> hi/lo bf16 [E,256] ----------------
__global__ void ln_pair_kernel(const float* __restrict__ xf,
                               const int* __restrict__ src, const int* __restrict__ dst,
                               const float* __restrict__ ln_g, const float* __restrict__ ln_b,
                               __nv_bfloat16* __restrict__ ph, __nv_bfloat16* __restrict__ pl, int E) {
    int e = blockIdx.x * 8 + (threadIdx.x >> 5);
    int lane = threadIdx.x & 31;
    if (e >= E) return;
    float4 a = ((const float4*)(xf + (size_t)src[e] * DD))[lane];
    float4 c = ((const float4*)(xf + (size_t)dst[e] * DD))[lane];
    float s  = a.x + a.y + a.z + a.w + c.x + c.y + c.z + c.w;
    float s2 = a.x * a.x + a.y * a.y + a.z * a.z + a.w * a.w
             + c.x * c.x + c.y * c.y + c.z * c.z + c.w * c.w;
#pragma unroll
    for (int o = 16; o; o >>= 1) {
        s  += __shfl_xor_sync(0xffffffffu, s,  o);
        s2 += __shfl_xor_sync(0xffffffffu, s2, o);
    }
    float mu = s * (1.f / 256.f);
    float var = s2 * (1.f / 256.f) - mu * mu;
    float rstd = rsqrtf(var + 1e-5f);
    int c0 = lane * 4;
    float4 g0 = *(const float4*)(ln_g + c0);
    float4 b0 = *(const float4*)(ln_b + c0);
    float4 g1 = *(const float4*)(ln_g + 128 + c0);
    float4 b1 = *(const float4*)(ln_b + 128 + c0);
    float o0[4], o1[4];
    o0[0] = fmaxf((a.x - mu) * rstd * g0.x + b0.x, 0.f);
    o0[1] = fmaxf((a.y - mu) * rstd * g0.y + b0.y, 0.f);
    o0[2] = fmaxf((a.z - mu) * rstd * g0.z + b0.z, 0.f);
    o0[3] = fmaxf((a.w - mu) * rstd * g0.w + b0.w, 0.f);
    o1[0] = fmaxf((c.x - mu) * rstd * g1.x + b1.x, 0.f);
    o1[1] = fmaxf((c.y - mu) * rstd * g1.y + b1.y, 0.f);
    o1[2] = fmaxf((c.z - mu) * rstd * g1.z + b1.z, 0.f);
    o1[3] = fmaxf((c.w - mu) * rstd * g1.w + b1.w, 0.f);
    union { __nv_bfloat16 b[4]; uint2 u; } hu, lu;
    size_t base = (size_t)e * 256 + c0;
#pragma unroll
    for (int j = 0; j < 4; j++) {
        __nv_bfloat16 h = __float2bfloat16(o0[j]);
        hu.b[j] = h; lu.b[j] = __float2bfloat16(o0[j] - __bfloat162float(h));
    }
    *(uint2*)(ph + base) = hu.u; *(uint2*)(pl + base) = lu.u;
#pragma unroll
    for (int j = 0; j < 4; j++) {
        __nv_bfloat16 h = __float2bfloat16(o1[j]);
        hu.b[j] = h; lu.b[j] = __float2bfloat16(o1[j] - __bfloat162float(h));
    }
    *(uint2*)(ph + base + 128) = hu.u; *(uint2*)(pl + base + 128) = lu.u;
}

// ---------------- dual gather ----------------
__global__ void dual_gather_kernel(const float* __restrict__ e_new, const int* __restrict__ idx,
                                   float* __restrict__ out, int E) {
    int row = blockIdx.x;
    int id = idx[row];
    float v = (id < E) ? e_new[(size_t)id * DD + threadIdx.x] : 1.0f;
    out[(size_t)row * DD + threadIdx.x] = v;
}

// ======================= launch =======================
extern "C" void kernel_launch(void* const* d_in, const int* in_sizes, int n_in,
                              void* d_out, int out_size) {
    const float* x         = (const float*)d_in[0];
    const int*   ei1       = (const int*)d_in[1];
    const int*   ei2       = (const int*)d_in[2];
    const int*   ei4       = (const int*)d_in[3];
    const int*   ei8       = (const int*)d_in[4];
    const float* dual_attr = (const float*)d_in[5];
    const float* edge_attr = (const float*)d_in[6];
    const int*   oemap     = (const int*)d_in[7];
    const float* Wl[4]  = {(const float*)d_in[8],  (const float*)d_in[12], (const float*)d_in[16], (const float*)d_in[20]};
    const float* Wr[4]  = {(const float*)d_in[9],  (const float*)d_in[13], (const float*)d_in[17], (const float*)d_in[21]};
    const float* att[4] = {(const float*)d_in[10], (const float*)d_in[14], (const float*)d_in[18], (const float*)d_in[22]};
    const float* bb[4]  = {(const float*)d_in[11], (const float*)d_in[15], (const float*)d_in[19], (const float*)d_in[23]};
    const float* We1    = (const float*)d_in[24];
    const float* fuse_W = (const float*)d_in[25];
    const float* fuse_b = (const float*)d_in[26];
    const float* ln_g   = (const float*)d_in[27];
    const float* ln_b   = (const float*)d_in[28];
    const float* mlp_W  = (const float*)d_in[29];
    const float* mlp_b  = (const float*)d_in[30];

    int N  = in_sizes[0] / DD;
    int Ec[4] = { in_sizes[1] / 2, in_sizes[2] / 2, in_sizes[3] / 2, in_sizes[4] / 2 };
    const int* eis[4] = { ei1, ei2, ei4, ei8 };
    int E   = Ec[0];
    int Moe = in_sizes[7];

    float* xf_out   = (float*)d_out;
    float* enew_out = xf_out + (size_t)N * DD;
    float* dual_out = enew_out + (size_t)E * DD;

    float *p_me1, *p_xl, *p_xr, *p_elog, *p_smax, *p_ssum, *p_cat;
    __nv_bfloat16 *p_whi, *p_wlo, *p_bh, *p_bl, *p_nh, *p_nl;
    cudaGetSymbolAddress((void**)&p_me1,  g_me1);
    cudaGetSymbolAddress((void**)&p_xl,   g_xl);
    cudaGetSymbolAddress((void**)&p_xr,   g_xr);
    cudaGetSymbolAddress((void**)&p_elog, g_elog);
    cudaGetSymbolAddress((void**)&p_smax, g_smax);
    cudaGetSymbolAddress((void**)&p_ssum, g_ssum);
    cudaGetSymbolAddress((void**)&p_cat,  g_cat);
    cudaGetSymbolAddress((void**)&p_whi,  g_Whi);
    cudaGetSymbolAddress((void**)&p_wlo,  g_Wlo);
    cudaGetSymbolAddress((void**)&p_bh,   g_bh);
    cudaGetSymbolAddress((void**)&p_bl,   g_bl);
    cudaGetSymbolAddress((void**)&p_nh,   g_nh);
    cudaGetSymbolAddress((void**)&p_nl,   g_nl);

    cudaFuncSetAttribute(mma_gemm_kernel, cudaFuncAttributeMaxDynamicSharedMemorySize, GEMM_SMEM);

    // weight offsets (elements)
    const int OWL = 0, OWR = 65536, OWE = 131072, OFU = 147456, OML = 212992;

    // ---- prep weights (transpose + hi/lo split) ----
    for (int c = 0; c < 4; c++) {
        wprep_kernel<<<64, 256>>>(Wl[c], p_whi + OWL + c * 16384, p_wlo + OWL + c * 16384, 128);
        wprep_kernel<<<64, 256>>>(Wr[c], p_whi + OWR + c * 16384, p_wlo + OWR + c * 16384, 128);
    }
    wprep_kernel<<<64, 256>>>(We1, p_whi + OWE, p_wlo + OWE, 128);
    wprep_kernel<<<256, 256>>>(fuse_W, p_whi + OFU, p_wlo + OFU, 512);
    wprep_kernel<<<128, 256>>>(mlp_W, p_whi + OML, p_wlo + OML, 256);

    // ---- me1 = dual_attr @ We1 ----
    asplit_kernel<<<(E * 32 + 255) / 256, 256>>>(dual_attr, p_bh, p_bl, E * 32);
    mma_gemm_kernel<<<(E + 127) / 128, 256, GEMM_SMEM>>>(
        p_bh, p_bl, E, 128, p_whi + OWE, p_wlo + OWE, nullptr, nullptr, p_me1);

    // ---- split x ----
    asplit_kernel<<<(N * 32 + 255) / 256, 256>>>(x, p_nh, p_nl, N * 32);

    // ---- 4 GAT convs ----
    int gN = (N + 127) / 128;
    for (int c = 0; c < 4; c++) {
        int Ecc = Ec[c];
        const int* src = eis[c];
        const int* dst = eis[c] + Ecc;

        mma_gemm_kernel<<<gN, 256, GEMM_SMEM>>>(p_nh, p_nl, N, 128,
            p_whi + OWL + c * 16384, p_wlo + OWL + c * 16384, nullptr, nullptr, p_xl);
        mma_gemm_kernel<<<gN, 256, GEMM_SMEM>>>(p_nh, p_nl, N, 128,
            p_whi + OWR + c * 16384, p_wlo + OWR + c * 16384, nullptr, nullptr, p_xr);

        fill_bias_kernel<<<(N * DD + 255) / 256, 256>>>(p_cat + (size_t)c * DD, bb[c], N);
        fill_kernel<<<(N * HHEADS + 255) / 256, 256>>>(p_smax, -INFINITY, N * HHEADS);
        fill_kernel<<<(N * HHEADS + 255) / 256, 256>>>(p_ssum, 0.f, N * HHEADS);

        edge_logits_kernel<<<(Ecc + 7) / 8, 256>>>(src, dst, Ecc, p_xl, p_xr,
                                                   (c == 0) ? p_me1 : nullptr,
                                                   att[c], p_elog, p_smax);
        edge_exp_kernel<<<(Ecc * HHEADS + 255) / 256, 256>>>(dst, Ecc, p_elog, p_smax, p_ssum);
        edge_agg_kernel<<<(Ecc + 7) / 8, 256>>>(src, dst, Ecc, p_elog, p_ssum, p_xl,
                                                p_cat + (size_t)c * DD);
    }

    // ---- fuse: xf = cat @ fuse_W + fuse_b ----
    asplit_kernel<<<(N * 128 + 255) / 256, 256>>>(p_cat, p_nh, p_nl, N * 128);
    mma_gemm_kernel<<<gN, 256, GEMM_SMEM>>>(p_nh, p_nl, N, 512,
        p_whi + OFU, p_wlo + OFU, fuse_b, nullptr, xf_out);

    // ---- LN over pairs -> bf16 hi/lo [E,256] ----
    ln_pair_kernel<<<(E + 7) / 8, 256>>>(xf_out, ei1, ei1 + E, ln_g, ln_b, p_bh, p_bl, E);

    // ---- edge MLP: enew = pair @ mlp_W + mlp_b + edge_attr ----
    mma_gemm_kernel<<<(E + 127) / 128, 256, GEMM_SMEM>>>(
        p_bh, p_bl, E, 256, p_whi + OML, p_wlo + OML, mlp_b, edge_attr, enew_out);

    // ---- dual gather ----
    dual_gather_kernel<<<Moe, DD>>>(enew_out, oemap, dual_out, E);
}

// round 8
// speedup vs baseline: 1.8719x; 1.1806x over previous
#include <cuda_runtime.h>
#include <cuda_bf16.h>
#include <math.h>
#include <stdint.h>

// ---------------- problem constants ----------------
#define DD     128
#define HHEADS 16
#define MAXN   50000
#define MAXE   500000

// ---------------- scratch (__device__ globals; no allocs allowed) ------
__device__ float g_me1 [MAXE * DD];                  // dual_attr @ We1 (fp32)
__device__ float g_xl  [MAXN * DD];
__device__ float g_xr  [MAXN * DD];
__device__ float g_elog[MAXE * HHEADS];
__device__ float g_smax[MAXN * HHEADS];
__device__ float g_ssum[MAXN * HHEADS];
__device__ float g_cat [MAXN * 4 * DD];
// dual_attr hi/lo split (E*128)
__device__ __nv_bfloat16 g_bh[MAXE * 128];
__device__ __nv_bfloat16 g_bl[MAXE * 128];
// node-side splits: x (N*128) then cat (N*512)
__device__ __nv_bfloat16 g_nh[MAXN * 512];
__device__ __nv_bfloat16 g_nl[MAXN * 512];
// weights, bf16 hi/lo, transposed to [N=128, K] K-major
#define WB_TOTAL 245760
__device__ __nv_bfloat16 g_Whi[WB_TOTAL];
__device__ __nv_bfloat16 g_Wlo[WB_TOTAL];

// ---------------- small helpers ----------------
__device__ __forceinline__ uint32_t smem_to_u32(const void* p) {
    uint32_t a;
    asm("{ .reg .u64 t; cvta.to.shared.u64 t, %1; cvt.u32.u64 %0, t; }" : "=r"(a) : "l"(p));
    return a;
}
__device__ __forceinline__ void atomicMaxF(float* addr, float v) {
    if (v >= 0.f) atomicMax((int*)addr, __float_as_int(v));
    else          atomicMin((unsigned int*)addr, __float_as_uint(v));
}

__device__ __forceinline__ void ldsm_x4(uint32_t addr, uint32_t* r) {
    asm volatile("ldmatrix.sync.aligned.m8n8.x4.shared.b16 {%0,%1,%2,%3}, [%4];"
                 : "=r"(r[0]), "=r"(r[1]), "=r"(r[2]), "=r"(r[3]) : "r"(addr));
}
__device__ __forceinline__ void mma_bf16(float* c, const uint32_t* a, const uint32_t* b) {
    asm volatile("mma.sync.aligned.m16n8k16.row.col.f32.bf16.bf16.f32 "
                 "{%0,%1,%2,%3}, {%4,%5,%6,%7}, {%8,%9}, {%0,%1,%2,%3};"
                 : "+f"(c[0]), "+f"(c[1]), "+f"(c[2]), "+f"(c[3])
                 : "r"(a[0]), "r"(a[1]), "r"(a[2]), "r"(a[3]), "r"(b[0]), "r"(b[1]));
}

// ============ bf16x3 HMMA GEMM ============
// C[M,128] = A[M,K] @ W[K,128]; A split hi/lo bf16 row-major [M,K];
// W split hi/lo bf16 as [128,K] K-major. fp32 accumulate.
#define SMA_HI 0
#define SMA_LO 16384
#define SMB_HI 32768
#define SMB_LO 49152
#define GEMM_SMEM 65536

__global__ void __launch_bounds__(256, 1) mma_gemm_kernel(
    const __nv_bfloat16* __restrict__ Ahi, const __nv_bfloat16* __restrict__ Alo,
    int M, int Ktot,
    const __nv_bfloat16* __restrict__ Bhi, const __nv_bfloat16* __restrict__ Blo,
    const float* __restrict__ bias, const float* __restrict__ res,
    float* __restrict__ C)
{
    extern __shared__ char smem[];
    uint32_t sb = smem_to_u32(smem);
    int tid = threadIdx.x, warp = tid >> 5, lane = tid & 31;
    int m0 = blockIdx.x * 128;
    int wm = (warp & 3) << 5, wn = (warp >> 2) << 6;
    int kt8 = Ktot >> 3;

    float acc[2][8][4];
#pragma unroll
    for (int i = 0; i < 2; i++)
#pragma unroll
        for (int j = 0; j < 8; j++)
#pragma unroll
            for (int q = 0; q < 4; q++) acc[i][j][q] = 0.f;

    const uint4 zero4 = make_uint4(0, 0, 0, 0);
    int nchunk = Ktot >> 6;
    for (int ch = 0; ch < nchunk; ch++) {
        if (ch) __syncthreads();
        int k8 = ch << 3;
        for (int t = tid; t < 1024; t += 256) {
            int row = t >> 3, seg = t & 7;
            uint32_t soff = (uint32_t)(row * 128 + ((seg ^ (row & 7)) << 4));
            int gr = m0 + row;
            uint4 vh = zero4, vl = zero4;
            if (gr < M) {
                size_t gi = (size_t)gr * kt8 + k8 + seg;
                vh = ((const uint4*)Ahi)[gi];
                vl = ((const uint4*)Alo)[gi];
            }
            *(uint4*)(smem + SMA_HI + soff) = vh;
            *(uint4*)(smem + SMA_LO + soff) = vl;
            size_t bi = (size_t)row * kt8 + k8 + seg;
            *(uint4*)(smem + SMB_HI + soff) = ((const uint4*)Bhi)[bi];
            *(uint4*)(smem + SMB_LO + soff) = ((const uint4*)Blo)[bi];
        }
        __syncthreads();

#pragma unroll
        for (int ks = 0; ks < 4; ks++) {
            uint32_t ah[2][4], al[2][4];
#pragma unroll
            for (int mi = 0; mi < 2; mi++) {
                int row = wm + mi * 16 + (lane & 15);
                int seg = ks * 2 + (lane >> 4);
                uint32_t ao = sb + (uint32_t)(row * 128 + ((seg ^ (row & 7)) << 4));
                ldsm_x4(ao + SMA_HI, ah[mi]);
                ldsm_x4(ao + SMA_LO, al[mi]);
            }
            uint32_t bh[8][2], bl[8][2];
#pragma unroll
            for (int nj = 0; nj < 8; nj += 2) {
                int n = wn + nj * 8 + ((lane >> 3) & 1) * 8 + (lane & 7);
                int seg = ks * 2 + (lane >> 4);
                uint32_t bo = sb + (uint32_t)(n * 128 + ((seg ^ (n & 7)) << 4));
                uint32_t th[4], tl[4];
                ldsm_x4(bo + SMB_HI, th);
                ldsm_x4(bo + SMB_LO, tl);
                bh[nj][0] = th[0]; bh[nj + 1][0] = th[1]; bh[nj][1] = th[2]; bh[nj + 1][1] = th[3];
                bl[nj][0] = tl[0]; bl[nj + 1][0] = tl[1]; bl[nj][1] = tl[2]; bl[nj + 1][1] = tl[3];
            }
#pragma unroll
            for (int mi = 0; mi < 2; mi++)
#pragma unroll
                for (int ni = 0; ni < 8; ni++) {
                    mma_bf16(acc[mi][ni], ah[mi], bh[ni]);
                    mma_bf16(acc[mi][ni], al[mi], bh[ni]);
                    mma_bf16(acc[mi][ni], ah[mi], bl[ni]);
                }
        }
    }

    int r0 = (lane >> 2), c0 = (lane & 3) * 2;
#pragma unroll
    for (int mi = 0; mi < 2; mi++) {
#pragma unroll
        for (int ni = 0; ni < 8; ni++) {
            int col = wn + ni * 8 + c0;
            float bx = 0.f, by = 0.f;
            if (bias) { bx = bias[col]; by = bias[col + 1]; }
#pragma unroll
            for (int h = 0; h < 2; h++) {
                int row = m0 + wm + mi * 16 + r0 + h * 8;
                if (row < M) {
                    float vx = acc[mi][ni][h * 2 + 0] + bx;
                    float vy = acc[mi][ni][h * 2 + 1] + by;
                    size_t oi = (size_t)row * 128 + col;
                    if (res) { vx += res[oi]; vy += res[oi + 1]; }
                    *(float2*)(C + oi) = make_float2(vx, vy);
                }
            }
        }
    }
}

// ============ fused edge MLP: gather -> LN -> ReLU -> bf16x3 HMMA -> +res ====
// block: 256 threads, 128 edges. smem: A hi/lo (4 chunk tiles) 128KB + B 32KB.
#define FSA_HI 0
#define FSA_LO 65536
#define FSB_HI 131072
#define FSB_LO 147456
#define FUSED_SMEM 163840

__global__ void __launch_bounds__(256, 1) fused_edge_mlp_kernel(
    const float* __restrict__ xf,
    const int* __restrict__ src, const int* __restrict__ dst,
    const float* __restrict__ ln_g, const float* __restrict__ ln_b,
    const __nv_bfloat16* __restrict__ Bhi, const __nv_bfloat16* __restrict__ Blo,
    const float* __restrict__ mlp_b, const float* __restrict__ eattr,
    float* __restrict__ out, int E)
{
    extern __shared__ char smem[];
    uint32_t sb = smem_to_u32(smem);
    int tid = threadIdx.x, warp = tid >> 5, lane = tid & 31;
    int e0 = blockIdx.x * 128;
    int c0 = lane * 4;

    float4 g0 = *(const float4*)(ln_g + c0);
    float4 b0 = *(const float4*)(ln_b + c0);
    float4 g1 = *(const float4*)(ln_g + 128 + c0);
    float4 b1 = *(const float4*)(ln_b + 128 + c0);

    // ---- gather + LN + ReLU + hi/lo split directly into swizzled A tiles ----
    for (int i = 0; i < 16; i++) {
        int row = warp * 16 + i;
        int e = e0 + row;
        float4 a = make_float4(0, 0, 0, 0), c = make_float4(0, 0, 0, 0);
        if (e < E) {
            a = *(const float4*)(xf + (size_t)src[e] * DD + c0);
            c = *(const float4*)(xf + (size_t)dst[e] * DD + c0);
        }
        float s  = a.x + a.y + a.z + a.w + c.x + c.y + c.z + c.w;
        float s2 = a.x * a.x + a.y * a.y + a.z * a.z + a.w * a.w
                 + c.x * c.x + c.y * c.y + c.z * c.z + c.w * c.w;
#pragma unroll
        for (int o = 16; o; o >>= 1) {
            s  += __shfl_xor_sync(0xffffffffu, s,  o);
            s2 += __shfl_xor_sync(0xffffffffu, s2, o);
        }
        float mu = s * (1.f / 256.f);
        float var = s2 * (1.f / 256.f) - mu * mu;
        float rstd = rsqrtf(var + 1e-5f);
        float o0[4], o1[4];
        o0[0] = fmaxf((a.x - mu) * rstd * g0.x + b0.x, 0.f);
        o0[1] = fmaxf((a.y - mu) * rstd * g0.y + b0.y, 0.f);
        o0[2] = fmaxf((a.z - mu) * rstd * g0.z + b0.z, 0.f);
        o0[3] = fmaxf((a.w - mu) * rstd * g0.w + b0.w, 0.f);
        o1[0] = fmaxf((c.x - mu) * rstd * g1.x + b1.x, 0.f);
        o1[1] = fmaxf((c.y - mu) * rstd * g1.y + b1.y, 0.f);
        o1[2] = fmaxf((c.z - mu) * rstd * g1.z + b1.z, 0.f);
        o1[3] = fmaxf((c.w - mu) * rstd * g1.w + b1.w, 0.f);
#pragma unroll
        for (int half = 0; half < 2; half++) {
            const float* o = half ? o1 : o0;
            int gcol = half * 128 + c0;
            int chunk = gcol >> 6, cc = gcol & 63;
            uint32_t off = (uint32_t)(chunk * 16384 + row * 128
                         + (((cc >> 3) ^ (row & 7)) << 4) + (cc & 7) * 2);
            union { __nv_bfloat16 b[4]; uint2 u; } hu, lu;
#pragma unroll
            for (int j = 0; j < 4; j++) {
                __nv_bfloat16 h = __float2bfloat16(o[j]);
                hu.b[j] = h;
                lu.b[j] = __float2bfloat16(o[j] - __bfloat162float(h));
            }
            *(uint2*)(smem + FSA_HI + off) = hu.u;
            *(uint2*)(smem + FSA_LO + off) = lu.u;
        }
    }

    // ---- MMA over K=256 in 4 chunks ----
    int wm = (warp & 3) << 5, wn = (warp >> 2) << 6;
    float acc[2][8][4];
#pragma unroll
    for (int i = 0; i < 2; i++)
#pragma unroll
        for (int j = 0; j < 8; j++)
#pragma unroll
            for (int q = 0; q < 4; q++) acc[i][j][q] = 0.f;

#pragma unroll
    for (int ch = 0; ch < 4; ch++) {
        for (int t = tid; t < 1024; t += 256) {
            int n = t >> 3, seg = t & 7;
            size_t gi = (size_t)n * 32 + ch * 8 + seg;
            uint32_t soff = (uint32_t)(n * 128 + ((seg ^ (n & 7)) << 4));
            *(uint4*)(smem + FSB_HI + soff) = ((const uint4*)Bhi)[gi];
            *(uint4*)(smem + FSB_LO + soff) = ((const uint4*)Blo)[gi];
        }
        __syncthreads();
        uint32_t abase = sb + (uint32_t)(FSA_HI + ch * 16384);
#pragma unroll
        for (int ks = 0; ks < 4; ks++) {
            uint32_t ah[2][4], al[2][4];
#pragma unroll
            for (int mi = 0; mi < 2; mi++) {
                int row = wm + mi * 16 + (lane & 15);
                int seg = ks * 2 + (lane >> 4);
                uint32_t ao = abase + (uint32_t)(row * 128 + ((seg ^ (row & 7)) << 4));
                ldsm_x4(ao, ah[mi]);
                ldsm_x4(ao + 65536, al[mi]);
            }
            uint32_t bh[8][2], bl[8][2];
#pragma unroll
            for (int nj = 0; nj < 8; nj += 2) {
                int n = wn + nj * 8 + ((lane >> 3) & 1) * 8 + (lane & 7);
                int seg = ks * 2 + (lane >> 4);
                uint32_t bo = sb + (uint32_t)(FSB_HI + n * 128 + ((seg ^ (n & 7)) << 4));
                uint32_t th[4], tl[4];
                ldsm_x4(bo, th);
                ldsm_x4(bo + 16384, tl);
                bh[nj][0] = th[0]; bh[nj + 1][0] = th[1]; bh[nj][1] = th[2]; bh[nj + 1][1] = th[3];
                bl[nj][0] = tl[0]; bl[nj + 1][0] = tl[1]; bl[nj][1] = tl[2]; bl[nj + 1][1] = tl[3];
            }
#pragma unroll
            for (int mi = 0; mi < 2; mi++)
#pragma unroll
                for (int ni = 0; ni < 8; ni++) {
                    mma_bf16(acc[mi][ni], ah[mi], bh[ni]);
                    mma_bf16(acc[mi][ni], al[mi], bh[ni]);
                    mma_bf16(acc[mi][ni], ah[mi], bl[ni]);
                }
        }
        __syncthreads();
    }

    // ---- epilogue: + mlp_b + edge_attr ----
    int r0 = (lane >> 2), cc0 = (lane & 3) * 2;
#pragma unroll
    for (int mi = 0; mi < 2; mi++) {
#pragma unroll
        for (int ni = 0; ni < 8; ni++) {
            int col = wn + ni * 8 + cc0;
            float bx = mlp_b[col], by = mlp_b[col + 1];
#pragma unroll
            for (int h = 0; h < 2; h++) {
                int row = e0 + wm + mi * 16 + r0 + h * 8;
                if (row < E) {
                    size_t oi = (size_t)row * 128 + col;
                    float vx = acc[mi][ni][h * 2 + 0] + bx + eattr[oi];
                    float vy = acc[mi][ni][h * 2 + 1] + by + eattr[oi + 1];
                    *(float2*)(out + oi) = make_float2(vx, vy);
                }
            }
        }
    }
}

// ============ weight prep: W[K,128] fp32 -> hi/lo bf16 [128,K] ============
__global__ void wprep_kernel(const float* __restrict__ W, __nv_bfloat16* __restrict__ hi,
                             __nv_bfloat16* __restrict__ lo, int K) {
    int i = blockIdx.x * 256 + threadIdx.x;
    if (i >= K * 128) return;
    int n = i / K, k = i - n * K;
    float v = W[(size_t)k * 128 + n];
    __nv_bfloat16 h = __float2bfloat16(v);
    hi[i] = h;
    lo[i] = __float2bfloat16(v - __bfloat162float(h));
}

// ============ activation split ============
__global__ void asplit_kernel(const float* __restrict__ A, __nv_bfloat16* __restrict__ hi,
                              __nv_bfloat16* __restrict__ lo, int n4) {
    int i = blockIdx.x * 256 + threadIdx.x;
    if (i >= n4) return;
    float4 v = ((const float4*)A)[i];
    union { __nv_bfloat16 b[4]; uint2 u; } hu, lu;
    float f[4] = { v.x, v.y, v.z, v.w };
#pragma unroll
    for (int j = 0; j < 4; j++) {
        __nv_bfloat16 h = __float2bfloat16(f[j]);
        hu.b[j] = h;
        lu.b[j] = __float2bfloat16(f[j] - __bfloat162float(h));
    }
    ((uint2*)hi)[i] = hu.u;
    ((uint2*)lo)[i] = lu.u;
}

// ---------------- misc fills ----------------
__global__ void fill_softmax_state_kernel(float* __restrict__ smax, float* __restrict__ ssum, int n) {
    int i = blockIdx.x * 256 + threadIdx.x;
    if (i < n) { smax[i] = -INFINITY; ssum[i] = 0.f; }
}
__global__ void fill_bias_kernel(float* __restrict__ cat, const float* __restrict__ bias, int N) {
    int i = blockIdx.x * 256 + threadIdx.x;
    if (i >= N * DD) return;
    int n = i >> 7, cc = i & 127;
    cat[(size_t)n * 512 + cc] = bias[cc];
}

// ---------------- edge logits ----------------
__global__ void edge_logits_kernel(const int* __restrict__ src, const int* __restrict__ dst, int E,
                                   const float* __restrict__ xl, const float* __restrict__ xr,
                                   const float* __restrict__ me, const float* __restrict__ att,
                                   float* __restrict__ elog, float* __restrict__ smax) {
    int e = blockIdx.x * 8 + (threadIdx.x >> 5);
    int lane = threadIdx.x & 31;
    if (e >= E) return;
    int s = src[e], d = dst[e];
    float4 a = *(const float4*)(xl + (size_t)s * DD + lane * 4);
    float4 b = *(const float4*)(xr + (size_t)d * DD + lane * 4);
    float4 mv = make_float4(a.x + b.x, a.y + b.y, a.z + b.z, a.w + b.w);
    if (me) {
        float4 c = *(const float4*)(me + (size_t)e * DD + lane * 4);
        mv.x += c.x; mv.y += c.y; mv.z += c.z; mv.w += c.w;
    }
    float4 at = *(const float4*)(att + lane * 4);
    float p = 0.f, m;
    m = mv.x; m = m > 0.f ? m : 0.2f * m; p += m * at.x;
    m = mv.y; m = m > 0.f ? m : 0.2f * m; p += m * at.y;
    m = mv.z; m = m > 0.f ? m : 0.2f * m; p += m * at.z;
    m = mv.w; m = m > 0.f ? m : 0.2f * m; p += m * at.w;
    p += __shfl_xor_sync(0xffffffffu, p, 1);
    if ((lane & 1) == 0) {
        int h = lane >> 1;
        elog[(size_t)e * HHEADS + h] = p;
        atomicMaxF(&smax[d * HHEADS + h], p);
    }
}

__global__ void edge_exp_kernel(const int* __restrict__ dst, int E,
                                float* __restrict__ elog, const float* __restrict__ smax,
                                float* __restrict__ ssum) {
    int t = blockIdx.x * 256 + threadIdx.x;
    if (t >= E * HHEADS) return;
    int e = t >> 4, h = t & 15;
    int d = dst[e];
    float v = __expf(elog[t] - smax[d * HHEADS + h]);
    elog[t] = v;
    atomicAdd(&ssum[d * HHEADS + h], v);
}

__global__ void edge_agg_kernel(const int* __restrict__ src, const int* __restrict__ dst, int E,
                                const float* __restrict__ elog, const float* __restrict__ ssum,
                                const float* __restrict__ xl, float* __restrict__ agg /*stride 512*/) {
    int e = blockIdx.x * 8 + (threadIdx.x >> 5);
    int lane = threadIdx.x & 31;
    if (e >= E) return;
    int s = src[e], d = dst[e];
    int h = lane >> 1;
    float al = elog[(size_t)e * HHEADS + h] / (ssum[d * HHEADS + h] + 1e-16f);
    float4 xs = *(const float4*)(xl + (size_t)s * DD + lane * 4);
    float* base = agg + (size_t)d * 512 + lane * 4;
    asm volatile("red.global.add.v4.f32 [%0], {%1, %2, %3, %4};"
                 :: "l"(base), "f"(al * xs.x), "f"(al * xs.y), "f"(al * xs.z), "f"(al * xs.w)
                 : "memory");
}

// ---------------- dual gather: warp per row, float4 ----------------
__global__ void dual_gather_kernel(const float* __restrict__ e_new, const int* __restrict__ idx,
                                   float* __restrict__ out, int E, int M) {
    int row = blockIdx.x * 8 + (threadIdx.x >> 5);
    if (row >= M) return;
    int lane = threadIdx.x & 31;
    int id = idx[row];
    float4 v = (id < E) ? *(const float4*)(e_new + (size_t)id * DD + lane * 4)
                        : make_float4(1.f, 1.f, 1.f, 1.f);
    *(float4*)(out + (size_t)row * DD + lane * 4) = v;
}

// ======================= launch =======================
extern "C" void kernel_launch(void* const* d_in, const int* in_sizes, int n_in,
                              void* d_out, int out_size) {
    const float* x         = (const float*)d_in[0];
    const int*   ei1       = (const int*)d_in[1];
    const int*   ei2       = (const int*)d_in[2];
    const int*   ei4       = (const int*)d_in[3];
    const int*   ei8       = (const int*)d_in[4];
    const float* dual_attr = (const float*)d_in[5];
    const float* edge_attr = (const float*)d_in[6];
    const int*   oemap     = (const int*)d_in[7];
    const float* Wl[4]  = {(const float*)d_in[8],  (const float*)d_in[12], (const float*)d_in[16], (const float*)d_in[20]};
    const float* Wr[4]  = {(const float*)d_in[9],  (const float*)d_in[13], (const float*)d_in[17], (const float*)d_in[21]};
    const float* att[4] = {(const float*)d_in[10], (const float*)d_in[14], (const float*)d_in[18], (const float*)d_in[22]};
    const float* bb[4]  = {(const float*)d_in[11], (const float*)d_in[15], (const float*)d_in[19], (const float*)d_in[23]};
    const float* We1    = (const float*)d_in[24];
    const float* fuse_W = (const float*)d_in[25];
    const float* fuse_b = (const float*)d_in[26];
    const float* ln_g   = (const float*)d_in[27];
    const float* ln_b   = (const float*)d_in[28];
    const float* mlp_W  = (const float*)d_in[29];
    const float* mlp_b  = (const float*)d_in[30];

    int N  = in_sizes[0] / DD;
    int Ec[4] = { in_sizes[1] / 2, in_sizes[2] / 2, in_sizes[3] / 2, in_sizes[4] / 2 };
    const int* eis[4] = { ei1, ei2, ei4, ei8 };
    int E   = Ec[0];
    int Moe = in_sizes[7];

    float* xf_out   = (float*)d_out;
    float* enew_out = xf_out + (size_t)N * DD;
    float* dual_out = enew_out + (size_t)E * DD;

    float *p_me1, *p_xl, *p_xr, *p_elog, *p_smax, *p_ssum, *p_cat;
    __nv_bfloat16 *p_whi, *p_wlo, *p_bh, *p_bl, *p_nh, *p_nl;
    cudaGetSymbolAddress((void**)&p_me1,  g_me1);
    cudaGetSymbolAddress((void**)&p_xl,   g_xl);
    cudaGetSymbolAddress((void**)&p_xr,   g_xr);
    cudaGetSymbolAddress((void**)&p_elog, g_elog);
    cudaGetSymbolAddress((void**)&p_smax, g_smax);
    cudaGetSymbolAddress((void**)&p_ssum, g_ssum);
    cudaGetSymbolAddress((void**)&p_cat,  g_cat);
    cudaGetSymbolAddress((void**)&p_whi,  g_Whi);
    cudaGetSymbolAddress((void**)&p_wlo,  g_Wlo);
    cudaGetSymbolAddress((void**)&p_bh,   g_bh);
    cudaGetSymbolAddress((void**)&p_bl,   g_bl);
    cudaGetSymbolAddress((void**)&p_nh,   g_nh);
    cudaGetSymbolAddress((void**)&p_nl,   g_nl);

    cudaFuncSetAttribute(mma_gemm_kernel, cudaFuncAttributeMaxDynamicSharedMemorySize, GEMM_SMEM);
    cudaFuncSetAttribute(fused_edge_mlp_kernel, cudaFuncAttributeMaxDynamicSharedMemorySize, FUSED_SMEM);

    // weight offsets (elements)
    const int OWL = 0, OWR = 65536, OWE = 131072, OFU = 147456, OML = 212992;

    // ---- prep weights ----
    for (int c = 0; c < 4; c++) {
        wprep_kernel<<<64, 256>>>(Wl[c], p_whi + OWL + c * 16384, p_wlo + OWL + c * 16384, 128);
        wprep_kernel<<<64, 256>>>(Wr[c], p_whi + OWR + c * 16384, p_wlo + OWR + c * 16384, 128);
    }
    wprep_kernel<<<64, 256>>>(We1, p_whi + OWE, p_wlo + OWE, 128);
    wprep_kernel<<<256, 256>>>(fuse_W, p_whi + OFU, p_wlo + OFU, 512);
    wprep_kernel<<<128, 256>>>(mlp_W, p_whi + OML, p_wlo + OML, 256);

    // ---- me1 = dual_attr @ We1 ----
    asplit_kernel<<<(E * 32 + 255) / 256, 256>>>(dual_attr, p_bh, p_bl, E * 32);
    mma_gemm_kernel<<<(E + 127) / 128, 256, GEMM_SMEM>>>(
        p_bh, p_bl, E, 128, p_whi + OWE, p_wlo + OWE, nullptr, nullptr, p_me1);

    // ---- split x ----
    asplit_kernel<<<(N * 32 + 255) / 256, 256>>>(x, p_nh, p_nl, N * 32);

    // ---- 4 GAT convs ----
    int gN = (N + 127) / 128;
    for (int c = 0; c < 4; c++) {
        int Ecc = Ec[c];
        const int* src = eis[c];
        const int* dst = eis[c] + Ecc;

        mma_gemm_kernel<<<gN, 256, GEMM_SMEM>>>(p_nh, p_nl, N, 128,
            p_whi + OWL + c * 16384, p_wlo + OWL + c * 16384, nullptr, nullptr, p_xl);
        mma_gemm_kernel<<<gN, 256, GEMM_SMEM>>>(p_nh, p_nl, N, 128,
            p_whi + OWR + c * 16384, p_wlo + OWR + c * 16384, nullptr, nullptr, p_xr);

        fill_bias_kernel<<<(N * DD + 255) / 256, 256>>>(p_cat + (size_t)c * DD, bb[c], N);
        fill_softmax_state_kernel<<<(N * HHEADS + 255) / 256, 256>>>(p_smax, p_ssum, N * HHEADS);

        edge_logits_kernel<<<(Ecc + 7) / 8, 256>>>(src, dst, Ecc, p_xl, p_xr,
                                                   (c == 0) ? p_me1 : nullptr,
                                                   att[c], p_elog, p_smax);
        edge_exp_kernel<<<(Ecc * HHEADS + 255) / 256, 256>>>(dst, Ecc, p_elog, p_smax, p_ssum);
        edge_agg_kernel<<<(Ecc + 7) / 8, 256>>>(src, dst, Ecc, p_elog, p_ssum, p_xl,
                                                p_cat + (size_t)c * DD);
    }

    // ---- fuse: xf = cat @ fuse_W + fuse_b ----
    asplit_kernel<<<(N * 128 + 255) / 256, 256>>>(p_cat, p_nh, p_nl, N * 128);
    mma_gemm_kernel<<<gN, 256, GEMM_SMEM>>>(p_nh, p_nl, N, 512,
        p_whi + OFU, p_wlo + OFU, fuse_b, nullptr, xf_out);

    // ---- fused LN + edge MLP (+residual) -> enew_out ----
    fused_edge_mlp_kernel<<<(E + 127) / 128, 256, FUSED_SMEM>>>(
        xf_out, ei1, ei1 + E, ln_g, ln_b,
        p_whi + OML, p_wlo + OML, mlp_b, edge_attr, enew_out, E);

    // ---- dual gather ----
    dual_gather_kernel<<<(Moe + 7) / 8, 256>>>(enew_out, oemap, dual_out, E, Moe);
}

// round 13
// speedup vs baseline: 2.3464x; 1.2535x over previous
#include <cuda_runtime.h>
#include <cuda_bf16.h>
#include <math.h>
#include <stdint.h>

// ---------------- problem constants ----------------
#define DD     128
#define HHEADS 16
#define MAXN   50000
#define MAXE   500000

// ---------------- scratch ----------------
__device__ float g_me1 [MAXE * DD];                  // dual_attr @ We1 (fp32)
__device__ float g_xlr [MAXN * 256];                 // [xl | xr] for current conv
__device__ float g_elog[MAXE * HHEADS];              // exp(logits)
__device__ float g_ssum[4 * MAXN * HHEADS];          // per-conv softmax denominators
__device__ float g_cat [MAXN * 4 * DD];              // concat agg (+bias), stride 512
// weights bf16 hi/lo: conv c combined [Wl;Wr] [256,128] @ c*32768 | we1 @131072 | fuse @147456 | mlp @212992
#define WB_TOTAL 245760
__device__ __nv_bfloat16 g_Whi[WB_TOTAL];
__device__ __nv_bfloat16 g_Wlo[WB_TOTAL];

// ---------------- helpers ----------------
__device__ __forceinline__ uint32_t smem_to_u32(const void* p) {
    uint32_t a;
    asm("{ .reg .u64 t; cvta.to.shared.u64 t, %1; cvt.u32.u64 %0, t; }" : "=r"(a) : "l"(p));
    return a;
}
__device__ __forceinline__ void ldsm_x4(uint32_t addr, uint32_t* r) {
    asm volatile("ldmatrix.sync.aligned.m8n8.x4.shared.b16 {%0,%1,%2,%3}, [%4];"
                 : "=r"(r[0]), "=r"(r[1]), "=r"(r[2]), "=r"(r[3]) : "r"(addr));
}
__device__ __forceinline__ void mma_bf16(float* c, const uint32_t* a, const uint32_t* b) {
    asm volatile("mma.sync.aligned.m16n8k16.row.col.f32.bf16.bf16.f32 "
                 "{%0,%1,%2,%3}, {%4,%5,%6,%7}, {%8,%9}, {%0,%1,%2,%3};"
                 : "+f"(c[0]), "+f"(c[1]), "+f"(c[2]), "+f"(c[3])
                 : "r"(a[0]), "r"(a[1]), "r"(a[2]), "r"(a[3]), "r"(b[0]), "r"(b[1]));
}

#define SMA_HI 0
#define SMA_LO 16384
#define SMB_HI 32768
#define SMB_LO 49152
#define GEMM_SMEM 65536

// ============ GEMM: C[:, n0:n0+128] = A[M,Ktot](fp32) @ B^T (+bias) ============
// A is fp32 row-major; hi/lo bf16 split happens during the smem tile store.
__global__ void __launch_bounds__(256, 1) mma_gemm_kernel(
    const float* __restrict__ A, int M, int Ktot,
    const __nv_bfloat16* __restrict__ Bhi, const __nv_bfloat16* __restrict__ Blo,
    const float* __restrict__ bias, float* __restrict__ C, int ldc)
{
    extern __shared__ char smem[];
    uint32_t sb = smem_to_u32(smem);
    int tid = threadIdx.x, warp = tid >> 5, lane = tid & 31;
    int m0 = blockIdx.x * 128;
    int n0 = blockIdx.y * 128;
    const __nv_bfloat16* bhi = Bhi + (size_t)n0 * Ktot;
    const __nv_bfloat16* blo = Blo + (size_t)n0 * Ktot;
    int wm = (warp & 3) << 5, wn = (warp >> 2) << 6;
    int kt8 = Ktot >> 3;

    float acc[2][8][4];
#pragma unroll
    for (int i = 0; i < 2; i++)
#pragma unroll
        for (int j = 0; j < 8; j++)
#pragma unroll
            for (int q = 0; q < 4; q++) acc[i][j][q] = 0.f;

    int nchunk = Ktot >> 6;
    for (int ch = 0; ch < nchunk; ch++) {
        if (ch) __syncthreads();
        int k0 = ch << 6;
        int k8 = ch << 3;
        // ---- load A (fp32 -> hi/lo) + B chunk into swizzled smem ----
        for (int t = tid; t < 1024; t += 256) {
            int row = t >> 3, seg = t & 7;
            uint32_t soff = (uint32_t)(row * 128 + ((seg ^ (row & 7)) << 4));
            int gr = m0 + row;
            float f[8] = {0, 0, 0, 0, 0, 0, 0, 0};
            if (gr < M) {
                const float* p = A + (size_t)gr * Ktot + k0 + seg * 8;
                float4 v0 = *(const float4*)p;
                float4 v1 = *(const float4*)(p + 4);
                f[0] = v0.x; f[1] = v0.y; f[2] = v0.z; f[3] = v0.w;
                f[4] = v1.x; f[5] = v1.y; f[6] = v1.z; f[7] = v1.w;
            }
            union { __nv_bfloat16 b[8]; uint4 u; } hu, lu;
#pragma unroll
            for (int j = 0; j < 8; j++) {
                __nv_bfloat16 h = __float2bfloat16(f[j]);
                hu.b[j] = h;
                lu.b[j] = __float2bfloat16(f[j] - __bfloat162float(h));
            }
            *(uint4*)(smem + SMA_HI + soff) = hu.u;
            *(uint4*)(smem + SMA_LO + soff) = lu.u;
            size_t bi = (size_t)row * kt8 + k8 + seg;
            *(uint4*)(smem + SMB_HI + soff) = ((const uint4*)bhi)[bi];
            *(uint4*)(smem + SMB_LO + soff) = ((const uint4*)blo)[bi];
        }
        __syncthreads();

#pragma unroll
        for (int ks = 0; ks < 4; ks++) {
            uint32_t ah[2][4], al[2][4];
#pragma unroll
            for (int mi = 0; mi < 2; mi++) {
                int row = wm + mi * 16 + (lane & 15);
                int seg = ks * 2 + (lane >> 4);
                uint32_t ao = sb + (uint32_t)(row * 128 + ((seg ^ (row & 7)) << 4));
                ldsm_x4(ao + SMA_HI, ah[mi]);
                ldsm_x4(ao + SMA_LO, al[mi]);
            }
            uint32_t bh[8][2], bl[8][2];
#pragma unroll
            for (int nj = 0; nj < 8; nj += 2) {
                int n = wn + nj * 8 + ((lane >> 3) & 1) * 8 + (lane & 7);
                int seg = ks * 2 + (lane >> 4);
                uint32_t bo = sb + (uint32_t)(n * 128 + ((seg ^ (n & 7)) << 4));
                uint32_t th[4], tl[4];
                ldsm_x4(bo + SMB_HI, th);
                ldsm_x4(bo + SMB_LO, tl);
                bh[nj][0] = th[0]; bh[nj + 1][0] = th[1]; bh[nj][1] = th[2]; bh[nj + 1][1] = th[3];
                bl[nj][0] = tl[0]; bl[nj + 1][0] = tl[1]; bl[nj][1] = tl[2]; bl[nj + 1][1] = tl[3];
            }
#pragma unroll
            for (int mi = 0; mi < 2; mi++)
#pragma unroll
                for (int ni = 0; ni < 8; ni++) {
                    mma_bf16(acc[mi][ni], ah[mi], bh[ni]);
                    mma_bf16(acc[mi][ni], al[mi], bh[ni]);
                    mma_bf16(acc[mi][ni], ah[mi], bl[ni]);
                }
        }
    }

    int r0 = (lane >> 2), c0 = (lane & 3) * 2;
#pragma unroll
    for (int mi = 0; mi < 2; mi++) {
#pragma unroll
        for (int ni = 0; ni < 8; ni++) {
            int col = wn + ni * 8 + c0;
            float bx = 0.f, by = 0.f;
            if (bias) { bx = bias[n0 + col]; by = bias[n0 + col + 1]; }
#pragma unroll
            for (int h = 0; h < 2; h++) {
                int row = m0 + wm + mi * 16 + r0 + h * 8;
                if (row < M) {
                    *(float2*)(C + (size_t)row * ldc + n0 + col) =
                        make_float2(acc[mi][ni][h * 2 + 0] + bx, acc[mi][ni][h * 2 + 1] + by);
                }
            }
        }
    }
}

// ============ fused edge MLP: gather -> LN -> ReLU -> bf16x3 HMMA -> +res ====
#define FSA_HI 0
#define FSA_LO 65536
#define FSB_HI 131072
#define FSB_LO 147456
#define FUSED_SMEM 163840

__global__ void __launch_bounds__(256, 1) fused_edge_mlp_kernel(
    const float* __restrict__ xf,
    const int* __restrict__ src, const int* __restrict__ dst,
    const float* __restrict__ ln_g, const float* __restrict__ ln_b,
    const __nv_bfloat16* __restrict__ Bhi, const __nv_bfloat16* __restrict__ Blo,
    const float* __restrict__ mlp_b, const float* __restrict__ eattr,
    float* __restrict__ out, int E)
{
    extern __shared__ char smem[];
    uint32_t sb = smem_to_u32(smem);
    int tid = threadIdx.x, warp = tid >> 5, lane = tid & 31;
    int e0 = blockIdx.x * 128;
    int c0 = lane * 4;

    float4 g0 = *(const float4*)(ln_g + c0);
    float4 b0 = *(const float4*)(ln_b + c0);
    float4 g1 = *(const float4*)(ln_g + 128 + c0);
    float4 b1 = *(const float4*)(ln_b + 128 + c0);

    for (int i = 0; i < 16; i++) {
        int row = warp * 16 + i;
        int e = e0 + row;
        float4 a = make_float4(0, 0, 0, 0), c = make_float4(0, 0, 0, 0);
        if (e < E) {
            a = *(const float4*)(xf + (size_t)src[e] * DD + c0);
            c = *(const float4*)(xf + (size_t)dst[e] * DD + c0);
        }
        float s  = a.x + a.y + a.z + a.w + c.x + c.y + c.z + c.w;
        float s2 = a.x * a.x + a.y * a.y + a.z * a.z + a.w * a.w
                 + c.x * c.x + c.y * c.y + c.z * c.z + c.w * c.w;
#pragma unroll
        for (int o = 16; o; o >>= 1) {
            s  += __shfl_xor_sync(0xffffffffu, s,  o);
            s2 += __shfl_xor_sync(0xffffffffu, s2, o);
        }
        float mu = s * (1.f / 256.f);
        float var = s2 * (1.f / 256.f) - mu * mu;
        float rstd = rsqrtf(var + 1e-5f);
        float o0[4], o1[4];
        o0[0] = fmaxf((a.x - mu) * rstd * g0.x + b0.x, 0.f);
        o0[1] = fmaxf((a.y - mu) * rstd * g0.y + b0.y, 0.f);
        o0[2] = fmaxf((a.z - mu) * rstd * g0.z + b0.z, 0.f);
        o0[3] = fmaxf((a.w - mu) * rstd * g0.w + b0.w, 0.f);
        o1[0] = fmaxf((c.x - mu) * rstd * g1.x + b1.x, 0.f);
        o1[1] = fmaxf((c.y - mu) * rstd * g1.y + b1.y, 0.f);
        o1[2] = fmaxf((c.z - mu) * rstd * g1.z + b1.z, 0.f);
        o1[3] = fmaxf((c.w - mu) * rstd * g1.w + b1.w, 0.f);
#pragma unroll
        for (int half = 0; half < 2; half++) {
            const float* o = half ? o1 : o0;
            int gcol = half * 128 + c0;
            int chunk = gcol >> 6, cc = gcol & 63;
            uint32_t off = (uint32_t)(chunk * 16384 + row * 128
                         + (((cc >> 3) ^ (row & 7)) << 4) + (cc & 7) * 2);
            union { __nv_bfloat16 b[4]; uint2 u; } hu, lu;
#pragma unroll
            for (int j = 0; j < 4; j++) {
                __nv_bfloat16 h = __float2bfloat16(o[j]);
                hu.b[j] = h;
                lu.b[j] = __float2bfloat16(o[j] - __bfloat162float(h));
            }
            *(uint2*)(smem + FSA_HI + off) = hu.u;
            *(uint2*)(smem + FSA_LO + off) = lu.u;
        }
    }

    int wm = (warp & 3) << 5, wn = (warp >> 2) << 6;
    float acc[2][8][4];
#pragma unroll
    for (int i = 0; i < 2; i++)
#pragma unroll
        for (int j = 0; j < 8; j++)
#pragma unroll
            for (int q = 0; q < 4; q++) acc[i][j][q] = 0.f;

#pragma unroll
    for (int ch = 0; ch < 4; ch++) {
        for (int t = tid; t < 1024; t += 256) {
            int n = t >> 3, seg = t & 7;
            size_t gi = (size_t)n * 32 + ch * 8 + seg;
            uint32_t soff = (uint32_t)(n * 128 + ((seg ^ (n & 7)) << 4));
            *(uint4*)(smem + FSB_HI + soff) = ((const uint4*)Bhi)[gi];
            *(uint4*)(smem + FSB_LO + soff) = ((const uint4*)Blo)[gi];
        }
        __syncthreads();
        uint32_t abase = sb + (uint32_t)(FSA_HI + ch * 16384);
#pragma unroll
        for (int ks = 0; ks < 4; ks++) {
            uint32_t ah[2][4], al[2][4];
#pragma unroll
            for (int mi = 0; mi < 2; mi++) {
                int row = wm + mi * 16 + (lane & 15);
                int seg = ks * 2 + (lane >> 4);
                uint32_t ao = abase + (uint32_t)(row * 128 + ((seg ^ (row & 7)) << 4));
                ldsm_x4(ao, ah[mi]);
                ldsm_x4(ao + 65536, al[mi]);
            }
            uint32_t bh[8][2], bl[8][2];
#pragma unroll
            for (int nj = 0; nj < 8; nj += 2) {
                int n = wn + nj * 8 + ((lane >> 3) & 1) * 8 + (lane & 7);
                int seg = ks * 2 + (lane >> 4);
                uint32_t bo = sb + (uint32_t)(FSB_HI + n * 128 + ((seg ^ (n & 7)) << 4));
                uint32_t th[4], tl[4];
                ldsm_x4(bo, th);
                ldsm_x4(bo + 16384, tl);
                bh[nj][0] = th[0]; bh[nj + 1][0] = th[1]; bh[nj][1] = th[2]; bh[nj + 1][1] = th[3];
                bl[nj][0] = tl[0]; bl[nj + 1][0] = tl[1]; bl[nj][1] = tl[2]; bl[nj + 1][1] = tl[3];
            }
#pragma unroll
            for (int mi = 0; mi < 2; mi++)
#pragma unroll
                for (int ni = 0; ni < 8; ni++) {
                    mma_bf16(acc[mi][ni], ah[mi], bh[ni]);
                    mma_bf16(acc[mi][ni], al[mi], bh[ni]);
                    mma_bf16(acc[mi][ni], ah[mi], bl[ni]);
                }
        }
        __syncthreads();
    }

    int r0 = (lane >> 2), cc0 = (lane & 3) * 2;
#pragma unroll
    for (int mi = 0; mi < 2; mi++) {
#pragma unroll
        for (int ni = 0; ni < 8; ni++) {
            int col = wn + ni * 8 + cc0;
            float bx = mlp_b[col], by = mlp_b[col + 1];
#pragma unroll
            for (int h = 0; h < 2; h++) {
                int row = e0 + wm + mi * 16 + r0 + h * 8;
                if (row < E) {
                    size_t oi = (size_t)row * 128 + col;
                    *(float2*)(out + oi) = make_float2(
                        acc[mi][ni][h * 2 + 0] + bx + eattr[oi],
                        acc[mi][ni][h * 2 + 1] + by + eattr[oi + 1]);
                }
            }
        }
    }
}

// ============ weight prep ============
struct WP9 { const float* src[9]; __nv_bfloat16* hi[9]; __nv_bfloat16* lo[9]; };
__global__ void wprep9_kernel(WP9 w) {
    int m = blockIdx.y;
    int i = blockIdx.x * 256 + threadIdx.x;
    if (i >= 128 * 128) return;
    int n = i >> 7, k = i & 127;
    float v = w.src[m][k * 128 + n];
    __nv_bfloat16 h = __float2bfloat16(v);
    w.hi[m][i] = h;
    w.lo[m][i] = __float2bfloat16(v - __bfloat162float(h));
}
__global__ void wprep_kernel(const float* __restrict__ W, __nv_bfloat16* __restrict__ hi,
                             __nv_bfloat16* __restrict__ lo, int K) {
    int i = blockIdx.x * 256 + threadIdx.x;
    if (i >= K * 128) return;
    int n = i / K, k = i - n * K;
    float v = W[(size_t)k * 128 + n];
    __nv_bfloat16 h = __float2bfloat16(v);
    hi[i] = h;
    lo[i] = __float2bfloat16(v - __bfloat162float(h));
}

// ---------------- init ----------------
__global__ void zero_kernel(float* __restrict__ p, int n) {
    int i = blockIdx.x * 256 + threadIdx.x;
    if (i < n) p[i] = 0.f;
}
__global__ void fill_bias4_kernel(float* __restrict__ cat,
                                  const float* __restrict__ b1, const float* __restrict__ b2,
                                  const float* __restrict__ b3, const float* __restrict__ b4,
                                  int N) {
    int i = blockIdx.x * 256 + threadIdx.x;
    if (i >= N * 512) return;
    int col = i & 511, c = col >> 7, cc = col & 127;
    const float* bs = (c == 0) ? b1 : (c == 1) ? b2 : (c == 2) ? b3 : b4;
    cat[i] = bs[cc];
}

// ---------------- logits + exp + ssum (warp per edge; optional me term) ----------------
__global__ void edge_logits_exp_kernel(const int* __restrict__ src, const int* __restrict__ dst, int E,
                                       const float* __restrict__ xlr, const float* __restrict__ me,
                                       const float* __restrict__ att,
                                       float* __restrict__ elog, float* __restrict__ ssum) {
    int e = blockIdx.x * 8 + (threadIdx.x >> 5);
    int lane = threadIdx.x & 31;
    if (e >= E) return;
    int s = src[e], d = dst[e];
    float4 a = *(const float4*)(xlr + (size_t)s * 256 + lane * 4);
    float4 b = *(const float4*)(xlr + (size_t)d * 256 + 128 + lane * 4);
    float4 mv = make_float4(a.x + b.x, a.y + b.y, a.z + b.z, a.w + b.w);
    if (me) {
        float4 c = *(const float4*)(me + (size_t)e * DD + lane * 4);
        mv.x += c.x; mv.y += c.y; mv.z += c.z; mv.w += c.w;
    }
    float4 at = *(const float4*)(att + lane * 4);
    float p = 0.f, m;
    m = mv.x; m = m > 0.f ? m : 0.2f * m; p += m * at.x;
    m = mv.y; m = m > 0.f ? m : 0.2f * m; p += m * at.y;
    m = mv.z; m = m > 0.f ? m : 0.2f * m; p += m * at.z;
    m = mv.w; m = m > 0.f ? m : 0.2f * m; p += m * at.w;
    p += __shfl_xor_sync(0xffffffffu, p, 1);
    if ((lane & 1) == 0) {
        int h = lane >> 1;
        float v = __expf(p);
        elog[(size_t)e * HHEADS + h] = v;
        atomicAdd(&ssum[d * HHEADS + h], v);
    }
}

// ---------------- weighted scatter-aggregate ----------------
__global__ void edge_agg_kernel(const int* __restrict__ src, const int* __restrict__ dst, int E,
                                const float* __restrict__ elog, const float* __restrict__ ssum,
                                const float* __restrict__ xlr, float* __restrict__ agg /*stride 512*/) {
    int e = blockIdx.x * 8 + (threadIdx.x >> 5);
    int lane = threadIdx.x & 31;
    if (e >= E) return;
    int s = src[e], d = dst[e];
    int h = lane >> 1;
    float al = elog[(size_t)e * HHEADS + h] / (ssum[d * HHEADS + h] + 1e-16f);
    float4 xs = *(const float4*)(xlr + (size_t)s * 256 + lane * 4);
    float* base = agg + (size_t)d * 512 + lane * 4;
    asm volatile("red.global.add.v4.f32 [%0], {%1, %2, %3, %4};"
                 :: "l"(base), "f"(al * xs.x), "f"(al * xs.y), "f"(al * xs.z), "f"(al * xs.w)
                 : "memory");
}

// ---------------- dual gather ----------------
__global__ void dual_gather_kernel(const float* __restrict__ e_new, const int* __restrict__ idx,
                                   float* __restrict__ out, int E, int M) {
    int row = blockIdx.x * 8 + (threadIdx.x >> 5);
    if (row >= M) return;
    int lane = threadIdx.x & 31;
    int id = idx[row];
    float4 v = (id < E) ? *(const float4*)(e_new + (size_t)id * DD + lane * 4)
                        : make_float4(1.f, 1.f, 1.f, 1.f);
    *(float4*)(out + (size_t)row * DD + lane * 4) = v;
}

// ======================= launch =======================
extern "C" void kernel_launch(void* const* d_in, const int* in_sizes, int n_in,
                              void* d_out, int out_size) {
    const float* x         = (const float*)d_in[0];
    const int*   ei1       = (const int*)d_in[1];
    const int*   ei2       = (const int*)d_in[2];
    const int*   ei4       = (const int*)d_in[3];
    const int*   ei8       = (const int*)d_in[4];
    const float* dual_attr = (const float*)d_in[5];
    const float* edge_attr = (const float*)d_in[6];
    const int*   oemap     = (const int*)d_in[7];
    const float* Wl[4]  = {(const float*)d_in[8],  (const float*)d_in[12], (const float*)d_in[16], (const float*)d_in[20]};
    const float* Wr[4]  = {(const float*)d_in[9],  (const float*)d_in[13], (const float*)d_in[17], (const float*)d_in[21]};
    const float* att[4] = {(const float*)d_in[10], (const float*)d_in[14], (const float*)d_in[18], (const float*)d_in[22]};
    const float* bb[4]  = {(const float*)d_in[11], (const float*)d_in[15], (const float*)d_in[19], (const float*)d_in[23]};
    const float* We1    = (const float*)d_in[24];
    const float* fuse_W = (const float*)d_in[25];
    const float* fuse_b = (const float*)d_in[26];
    const float* ln_g   = (const float*)d_in[27];
    const float* ln_b   = (const float*)d_in[28];
    const float* mlp_W  = (const float*)d_in[29];
    const float* mlp_b  = (const float*)d_in[30];

    int N  = in_sizes[0] / DD;
    int Ec[4] = { in_sizes[1] / 2, in_sizes[2] / 2, in_sizes[3] / 2, in_sizes[4] / 2 };
    const int* eis[4] = { ei1, ei2, ei4, ei8 };
    int E   = Ec[0];
    int Moe = in_sizes[7];

    float* xf_out   = (float*)d_out;
    float* enew_out = xf_out + (size_t)N * DD;
    float* dual_out = enew_out + (size_t)E * DD;

    float *p_me1, *p_xlr, *p_elog, *p_ssum, *p_cat;
    __nv_bfloat16 *p_whi, *p_wlo;
    cudaGetSymbolAddress((void**)&p_me1,  g_me1);
    cudaGetSymbolAddress((void**)&p_xlr,  g_xlr);
    cudaGetSymbolAddress((void**)&p_elog, g_elog);
    cudaGetSymbolAddress((void**)&p_ssum, g_ssum);
    cudaGetSymbolAddress((void**)&p_cat,  g_cat);
    cudaGetSymbolAddress((void**)&p_whi,  g_Whi);
    cudaGetSymbolAddress((void**)&p_wlo,  g_Wlo);

    cudaFuncSetAttribute(mma_gemm_kernel, cudaFuncAttributeMaxDynamicSharedMemorySize, GEMM_SMEM);
    cudaFuncSetAttribute(fused_edge_mlp_kernel, cudaFuncAttributeMaxDynamicSharedMemorySize, FUSED_SMEM);

    // weight offsets (elements): conv c combined [256,128] @ c*32768 (Wl rows 0-127, Wr rows 128-255)
    const int OWE = 131072, OFU = 147456, OML = 212992;

    // ---- weight prep: 9x [128,128] in one launch + fuse + mlp ----
    WP9 wp;
    for (int c = 0; c < 4; c++) {
        wp.src[2 * c]     = Wl[c]; wp.hi[2 * c]     = p_whi + c * 32768;         wp.lo[2 * c]     = p_wlo + c * 32768;
        wp.src[2 * c + 1] = Wr[c]; wp.hi[2 * c + 1] = p_whi + c * 32768 + 16384; wp.lo[2 * c + 1] = p_wlo + c * 32768 + 16384;
    }
    wp.src[8] = We1; wp.hi[8] = p_whi + OWE; wp.lo[8] = p_wlo + OWE;
    wprep9_kernel<<<dim3(64, 9), 256>>>(wp);
    wprep_kernel<<<256, 256>>>(fuse_W, p_whi + OFU, p_wlo + OFU, 512);
    wprep_kernel<<<128, 256>>>(mlp_W, p_whi + OML, p_wlo + OML, 256);

    // ---- init: all 4 ssum buffers + cat biases ----
    zero_kernel<<<(4 * MAXN * HHEADS + 255) / 256, 256>>>(p_ssum, 4 * MAXN * HHEADS);
    fill_bias4_kernel<<<(N * 512 + 255) / 256, 256>>>(p_cat, bb[0], bb[1], bb[2], bb[3], N);

    // ---- me1 = dual_attr @ We1 (fp32 A, inline split) ----
    mma_gemm_kernel<<<dim3((E + 127) / 128, 1), 256, GEMM_SMEM>>>(
        dual_attr, E, 128, p_whi + OWE, p_wlo + OWE, nullptr, p_me1, 128);

    int gN = (N + 127) / 128;

    // ---- 4 GAT convs ----
    for (int c = 0; c < 4; c++) {
        int Ecc = Ec[c];
        const int* src = eis[c];
        const int* dst = eis[c] + Ecc;
        float* ssum_c = p_ssum + (size_t)c * MAXN * HHEADS;

        // xlr = x @ [Wl|Wr]^T : [N,256]
        mma_gemm_kernel<<<dim3(gN, 2), 256, GEMM_SMEM>>>(
            x, N, 128, p_whi + c * 32768, p_wlo + c * 32768, nullptr, p_xlr, 256);

        edge_logits_exp_kernel<<<(Ecc + 7) / 8, 256>>>(src, dst, Ecc, p_xlr,
                                                       (c == 0) ? p_me1 : nullptr,
                                                       att[c], p_elog, ssum_c);
        edge_agg_kernel<<<(Ecc + 7) / 8, 256>>>(src, dst, Ecc, p_elog, ssum_c, p_xlr,
                                                p_cat + (size_t)c * DD);
    }

    // ---- fuse: xf = cat @ fuse_W + fuse_b ----
    mma_gemm_kernel<<<dim3(gN, 1), 256, GEMM_SMEM>>>(
        p_cat, N, 512, p_whi + OFU, p_wlo + OFU, fuse_b, xf_out, 128);

    // ---- fused LN + edge MLP (+residual) -> enew_out ----
    fused_edge_mlp_kernel<<<(E + 127) / 128, 256, FUSED_SMEM>>>(
        xf_out, ei1, ei1 + E, ln_g, ln_b,
        p_whi + OML, p_wlo + OML, mlp_b, edge_attr, enew_out, E);

    // ---- dual gather ----
    dual_gather_kernel<<<(Moe + 7) / 8, 256>>>(enew_out, oemap, dual_out, E, Moe);
}